// round 9
// baseline (speedup 1.0000x reference)
#include <cuda_runtime.h>

#define BB 16
#define SS 4096
#define VV 1024
#define INV_SQRT_S 0.015625f   // 1/sqrt(4096)
#define NB 592                 // 148 SMs x 4 CTAs: one resident wave (K1)

// Scratch (no allocations allowed)
__device__ float g_q[BB * VV];
__device__ float g_u[BB * VV];
__device__ float g_c[BB];
__device__ float g_y[BB * VV];
__device__ float g_A[BB];

// Device-wide sense-reversal barrier (generation-based: safe across graph replays)
__device__ unsigned g_barcnt = 0;
__device__ volatile unsigned g_bargen = 0;

__device__ __forceinline__ void gbar() {
    __syncthreads();
    if (threadIdx.x == 0) {
        __threadfence();
        unsigned gen = g_bargen;
        if (atomicAdd(&g_barcnt, 1u) == NB - 1u) {
            g_barcnt = 0;
            __threadfence();
            g_bargen = gen + 1u;
        } else {
            while (g_bargen == gen) __nanosleep(64);
        }
    }
    __syncthreads();
    __threadfence();
}

// ---------------------------------------------------------------------------
// K1: prep kernel.  Phase A: q = Wq@pool + bq (256 blocks; Wq read once)
//                   + zero g_u/g_y/g_A (336 blocks).   [gbar]
//                   Phase B: u = q @ Wk (512 blocks; Wk read once);
//                            c[b] = q[b].bk (16 blocks).
// ---------------------------------------------------------------------------
__global__ void __launch_bounds__(128, 4) prep_kernel(
        const float* __restrict__ pool,
        const float* __restrict__ Wq, const float* __restrict__ bq,
        const float* __restrict__ Wk, const float* __restrict__ bk) {
    const int warp = threadIdx.x >> 5, lane = threadIdx.x & 31;
    __shared__ float sh[BB * 256];   // 16 KB

    // ---------- Phase A ----------
    if (blockIdx.x < 256) {
        const int o = blockIdx.x * 4 + warp;
        float acc[16];
#pragma unroll
        for (int b = 0; b < 16; b++) acc[b] = 0.f;

        for (int ch = 0; ch < 4; ch++) {
            __syncthreads();
            for (int i = threadIdx.x; i < 4096; i += 128) {
                int b = i >> 8, v = i & 255;
                sh[i] = pool[(size_t)b * VV + ch * 256 + v];
            }
            __syncthreads();
#pragma unroll
            for (int j = 0; j < 8; j++) {
                float w = Wq[(size_t)o * VV + ch * 256 + j * 32 + lane];
#pragma unroll
                for (int b = 0; b < 16; b++)
                    acc[b] = fmaf(w, sh[b * 256 + j * 32 + lane], acc[b]);
            }
        }
#pragma unroll
        for (int b = 0; b < 16; b++) {
#pragma unroll
            for (int off = 16; off; off >>= 1)
                acc[b] += __shfl_xor_sync(0xffffffffu, acc[b], off);
        }
        if (lane == 0) {
            float bqo = bq[o];
#pragma unroll
            for (int b = 0; b < 16; b++) g_q[(size_t)b * VV + o] = acc[b] + bqo;
        }
    } else {
        int t = (blockIdx.x - 256) * 128 + threadIdx.x;
        if (t < BB * VV) { g_u[t] = 0.f; g_y[t] = 0.f; }
        if (t < BB) g_A[t] = 0.f;
    }
    gbar();

    // ---------- Phase B ----------
    if (blockIdx.x < 512) {
        const int o0 = (blockIdx.x >> 3) * 16;
        const int v = (blockIdx.x & 7) * 128 + threadIdx.x;

        for (int i = threadIdx.x; i < 256; i += 128) {
            int b = i >> 4, oo = i & 15;
            sh[i] = g_q[(size_t)b * VV + o0 + oo];
        }
        __syncthreads();

        float acc[16];
#pragma unroll
        for (int b = 0; b < 16; b++) acc[b] = 0.f;
#pragma unroll
        for (int oo = 0; oo < 16; oo++) {
            float w = Wk[(size_t)(o0 + oo) * VV + v];
#pragma unroll
            for (int b = 0; b < 16; b++)
                acc[b] = fmaf(sh[b * 16 + oo], w, acc[b]);
        }
#pragma unroll
        for (int b = 0; b < 16; b++)
            atomicAdd(&g_u[(size_t)b * VV + v], acc[b]);
    } else if (blockIdx.x < 528) {
        const int b = blockIdx.x - 512;
        float s = 0.f;
#pragma unroll
        for (int j = 0; j < 8; j++) {
            int o = j * 128 + threadIdx.x;
            s = fmaf(g_q[(size_t)b * VV + o], bk[o], s);
        }
#pragma unroll
        for (int off = 16; off; off >>= 1) s += __shfl_xor_sync(0xffffffffu, s, off);
        if (lane == 0) sh[warp] = s;
        __syncthreads();
        if (threadIdx.x == 0) g_c[b] = sh[0] + sh[1] + sh[2] + sh[3];
    }
}

// ---------------------------------------------------------------------------
// K2: main pass — BIT-IDENTICAL structure to R4's 45.2us main_kernel.
// ---------------------------------------------------------------------------
__global__ void __launch_bounds__(128, 4) main_kernel(const float* __restrict__ X) {
    const int b = blockIdx.y;
    const int warp = threadIdx.x >> 5, lane = threadIdx.x & 31;
    const int wg = blockIdx.x * 4 + warp;   // 0..147

    float4 u4[8];
    const float4* ub = reinterpret_cast<const float4*>(g_u + (size_t)b * VV);
#pragma unroll
    for (int j = 0; j < 8; j++) u4[j] = ub[j * 32 + lane];
    const float cb = g_c[b];

    float yacc[32];
#pragma unroll
    for (int i = 0; i < 32; i++) yacc[i] = 0.f;
    float Aacc = 0.f;

    const float4* Xb = reinterpret_cast<const float4*>(X + (size_t)b * SS * VV);

    for (int row = wg; row < SS; row += 148) {
        const float4* xr = Xb + (size_t)row * (VV / 4);
        float4 x4[8];
#pragma unroll
        for (int j = 0; j < 8; j++) x4[j] = xr[j * 32 + lane];

        float p[8];
#pragma unroll
        for (int j = 0; j < 8; j++)
            p[j] = fmaf(x4[j].w, u4[j].w,
                   fmaf(x4[j].z, u4[j].z,
                   fmaf(x4[j].y, u4[j].y, x4[j].x * u4[j].x)));
        float d = ((p[0] + p[1]) + (p[2] + p[3])) + ((p[4] + p[5]) + (p[6] + p[7]));
#pragma unroll
        for (int off = 16; off; off >>= 1) d += __shfl_xor_sync(0xffffffffu, d, off);

        const float a = (d + cb) * INV_SQRT_S;
        Aacc += a;
#pragma unroll
        for (int j = 0; j < 8; j++) {
            yacc[j * 4 + 0] = fmaf(a, x4[j].x, yacc[j * 4 + 0]);
            yacc[j * 4 + 1] = fmaf(a, x4[j].y, yacc[j * 4 + 1]);
            yacc[j * 4 + 2] = fmaf(a, x4[j].z, yacc[j * 4 + 2]);
            yacc[j * 4 + 3] = fmaf(a, x4[j].w, yacc[j * 4 + 3]);
        }
    }

    __shared__ float ys[VV];
    __shared__ float As;
    for (int i = threadIdx.x; i < VV; i += 128) ys[i] = 0.f;
    if (threadIdx.x == 0) As = 0.f;
    __syncthreads();
#pragma unroll
    for (int j = 0; j < 8; j++) {
        int col = j * 128 + lane * 4;
        atomicAdd(&ys[col + 0], yacc[j * 4 + 0]);
        atomicAdd(&ys[col + 1], yacc[j * 4 + 1]);
        atomicAdd(&ys[col + 2], yacc[j * 4 + 2]);
        atomicAdd(&ys[col + 3], yacc[j * 4 + 3]);
    }
    if (lane == 0) atomicAdd(&As, Aacc);
    __syncthreads();
    for (int i = threadIdx.x; i < VV; i += 128)
        atomicAdd(&g_y[(size_t)b * VV + i], ys[i]);
    if (threadIdx.x == 0) atomicAdd(&g_A[b], As);
}

// ---------------------------------------------------------------------------
// K3: epilogue — out[b][o] = Wv[o].y[b] + A[b]*bv[o]  (Wv read once)
// ---------------------------------------------------------------------------
__global__ void __launch_bounds__(128) epilogue_kernel(const float* __restrict__ Wv,
                                                       const float* __restrict__ bv,
                                                       float* __restrict__ out) {
    const int warp = threadIdx.x >> 5, lane = threadIdx.x & 31;
    const int o = blockIdx.x * 4 + warp;
    __shared__ float sh[BB * 256];
    float acc[16];
#pragma unroll
    for (int b = 0; b < 16; b++) acc[b] = 0.f;

    for (int ch = 0; ch < 4; ch++) {
        __syncthreads();
        for (int i = threadIdx.x; i < 4096; i += 128) {
            int b = i >> 8, v = i & 255;
            sh[i] = g_y[(size_t)b * VV + ch * 256 + v];
        }
        __syncthreads();
#pragma unroll
        for (int j = 0; j < 8; j++) {
            float w = Wv[(size_t)o * VV + ch * 256 + j * 32 + lane];
#pragma unroll
            for (int b = 0; b < 16; b++)
                acc[b] = fmaf(w, sh[b * 256 + j * 32 + lane], acc[b]);
        }
    }
#pragma unroll
    for (int b = 0; b < 16; b++) {
#pragma unroll
        for (int off = 16; off; off >>= 1)
            acc[b] += __shfl_xor_sync(0xffffffffu, acc[b], off);
    }
    if (lane == 0) {
        float bvo = bv[o];
#pragma unroll
        for (int b = 0; b < 16; b++)
            out[(size_t)b * VV + o] = acc[b] + g_A[b] * bvo;
    }
}

// ---------------------------------------------------------------------------
extern "C" void kernel_launch(void* const* d_in, const int* in_sizes, int n_in,
                              void* d_out, int out_size) {
    const float* pool = (const float*)d_in[0];
    const float* bert = (const float*)d_in[1];
    const float* Wq   = (const float*)d_in[2];
    const float* bq   = (const float*)d_in[3];
    const float* Wk   = (const float*)d_in[4];
    const float* bk   = (const float*)d_in[5];
    const float* Wv   = (const float*)d_in[6];
    const float* bv   = (const float*)d_in[7];
    float* out = (float*)d_out;

    prep_kernel<<<NB, 128>>>(pool, Wq, bq, Wk, bk);
    dim3 mg(37, 16);
    main_kernel<<<mg, 128>>>(bert);
    epilogue_kernel<<<256, 128>>>(Wv, bv, out);
}

// round 10
// speedup vs baseline: 1.3178x; 1.3178x over previous
#include <cuda_runtime.h>

#define BB 16
#define SS 4096
#define VV 1024
#define INV_SQRT_S 0.015625f   // 1/sqrt(4096)
#define NB 592                 // 148 SMs x 4 CTAs: exactly one resident wave

// Scratch (no allocations allowed)
__device__ float g_qp[2][BB * VV];   // q partials (v-halves)
__device__ float g_u[BB * VV];
__device__ float g_c[BB];
__device__ float g_y[BB * VV];
__device__ float g_A[BB];

// Device-wide sense-reversal barrier (generation-based: safe across graph replays)
__device__ unsigned g_barcnt = 0;
__device__ volatile unsigned g_bargen = 0;

__device__ __forceinline__ void gbar() {
    __syncthreads();
    if (threadIdx.x == 0) {
        __threadfence();
        unsigned gen = g_bargen;
        if (atomicAdd(&g_barcnt, 1u) == NB - 1u) {
            g_barcnt = 0;
            __threadfence();
            g_bargen = gen + 1u;
        } else {
            while (g_bargen == gen) __nanosleep(64);
        }
    }
    __syncthreads();
    __threadfence();
}

// ---------------------------------------------------------------------------
// Single persistent kernel:
//   A: q partials (512 blocks: o x v-half split; Wq read once; no atomics)
//      + zeroing of g_u/g_y/g_A by blocks 512..591
//   B: u = q @ Wk (512 blocks, q = sum of partials staged in smem, Wk read
//      once); c[b] = q[b].bk (16 blocks, exact)
//   C: fused main pass over bert_output (268 MB single read)
//   D: out = Wv @ y + A*bv (256 blocks, y chunks staged in smem; Wv read once)
// ---------------------------------------------------------------------------
__global__ void __launch_bounds__(128, 4) fused_kernel(
        const float* __restrict__ pool, const float* __restrict__ X,
        const float* __restrict__ Wq, const float* __restrict__ bq,
        const float* __restrict__ Wk, const float* __restrict__ bk,
        const float* __restrict__ Wv, const float* __restrict__ bv,
        float* __restrict__ out) {
    const int warp = threadIdx.x >> 5, lane = threadIdx.x & 31;
    __shared__ float sh[BB * 256];   // 16 KB staging buffer, reused per phase
    __shared__ float shA;

    // ---------- Phase A: q partial over v-half ----------
    if (blockIdx.x < 512) {
        const int vh = blockIdx.x & 1;                 // v-half: 0 or 1
        const int o = (blockIdx.x >> 1) * 4 + warp;    // 0..1023
        const int vbase = vh * 512;
        float acc[16];
#pragma unroll
        for (int b = 0; b < 16; b++) acc[b] = 0.f;

#pragma unroll
        for (int ch = 0; ch < 2; ch++) {
            __syncthreads();
            for (int i = threadIdx.x; i < 4096; i += 128) {
                int b = i >> 8, v = i & 255;
                sh[i] = pool[(size_t)b * VV + vbase + ch * 256 + v];
            }
            __syncthreads();
#pragma unroll
            for (int j = 0; j < 8; j++) {
                float w = Wq[(size_t)o * VV + vbase + ch * 256 + j * 32 + lane];
#pragma unroll
                for (int b = 0; b < 16; b++)
                    acc[b] = fmaf(w, sh[b * 256 + j * 32 + lane], acc[b]);
            }
        }
#pragma unroll
        for (int b = 0; b < 16; b++) {
#pragma unroll
            for (int off = 16; off; off >>= 1)
                acc[b] += __shfl_xor_sync(0xffffffffu, acc[b], off);
        }
        if (lane == 0) {
            float bqo = (vh == 0) ? bq[o] : 0.f;
#pragma unroll
            for (int b = 0; b < 16; b++)
                g_qp[vh][(size_t)b * VV + o] = acc[b] + bqo;
        }
    } else {
        // blocks 512..591 zero the accumulators (80 blocks, 10240 threads)
        for (int t = (blockIdx.x - 512) * 128 + threadIdx.x; t < BB * VV;
             t += 80 * 128) {
            g_u[t] = 0.f; g_y[t] = 0.f;
        }
        if (blockIdx.x == 512 && threadIdx.x < BB) g_A[threadIdx.x] = 0.f;
    }
    gbar();

    // ---------- Phase B: u[b][v] = sum_o q[b][o]*Wk[o][v];  c[b] = q[b].bk ----------
    if (blockIdx.x < 512) {
        const int o0 = (blockIdx.x >> 3) * 16;
        const int v = (blockIdx.x & 7) * 128 + threadIdx.x;

        // q chunk [16 b][16 o], q = sum of the two v-half partials
        for (int i = threadIdx.x; i < 256; i += 128) {
            int b = i >> 4, oo = i & 15;
            size_t idx = (size_t)b * VV + o0 + oo;
            sh[i] = g_qp[0][idx] + g_qp[1][idx];
        }
        __syncthreads();

        float acc[16];
#pragma unroll
        for (int b = 0; b < 16; b++) acc[b] = 0.f;
#pragma unroll
        for (int oo = 0; oo < 16; oo++) {
            float w = Wk[(size_t)(o0 + oo) * VV + v];
#pragma unroll
            for (int b = 0; b < 16; b++)
                acc[b] = fmaf(sh[b * 16 + oo], w, acc[b]);
        }
#pragma unroll
        for (int b = 0; b < 16; b++)
            atomicAdd(&g_u[(size_t)b * VV + v], acc[b]);
    } else if (blockIdx.x < 528) {
        // c[b] = dot(q[b], bk): one block per b, exact write (no atomics)
        const int b = blockIdx.x - 512;
        float s = 0.f;
#pragma unroll
        for (int j = 0; j < 8; j++) {
            int o = j * 128 + threadIdx.x;
            size_t idx = (size_t)b * VV + o;
            s = fmaf(g_qp[0][idx] + g_qp[1][idx], bk[o], s);
        }
#pragma unroll
        for (int off = 16; off; off >>= 1) s += __shfl_xor_sync(0xffffffffu, s, off);
        if (lane == 0) sh[warp] = s;
        __syncthreads();
        if (threadIdx.x == 0) g_c[b] = sh[0] + sh[1] + sh[2] + sh[3];
    }
    gbar();

    // ---------- Phase C: fused main pass over bert_output ----------
    {
        const int b = blockIdx.x & 15;
        const int grp = blockIdx.x >> 4;          // 0..36
        const int wg = grp * 4 + warp;            // 0..147

        float4 u4[8];
        const float4* ub = (const float4*)(g_u + (size_t)b * VV);
#pragma unroll
        for (int j = 0; j < 8; j++) u4[j] = ub[j * 32 + lane];
        const float cb = g_c[b];

        float yacc[32];
#pragma unroll
        for (int i = 0; i < 32; i++) yacc[i] = 0.f;
        float Aacc = 0.f;

        const float4* Xb = (const float4*)(X + (size_t)b * SS * VV);
        for (int row = wg; row < SS; row += 148) {
            const float4* xr = Xb + (size_t)row * (VV / 4);
            float4 x4[8];
#pragma unroll
            for (int j = 0; j < 8; j++) x4[j] = xr[j * 32 + lane];

            float p[8];
#pragma unroll
            for (int j = 0; j < 8; j++)
                p[j] = fmaf(x4[j].w, u4[j].w,
                       fmaf(x4[j].z, u4[j].z,
                       fmaf(x4[j].y, u4[j].y, x4[j].x * u4[j].x)));
            float d = ((p[0] + p[1]) + (p[2] + p[3])) + ((p[4] + p[5]) + (p[6] + p[7]));
#pragma unroll
            for (int off = 16; off; off >>= 1) d += __shfl_xor_sync(0xffffffffu, d, off);

            const float a = (d + cb) * INV_SQRT_S;
            Aacc += a;
#pragma unroll
            for (int j = 0; j < 8; j++) {
                yacc[j * 4 + 0] = fmaf(a, x4[j].x, yacc[j * 4 + 0]);
                yacc[j * 4 + 1] = fmaf(a, x4[j].y, yacc[j * 4 + 1]);
                yacc[j * 4 + 2] = fmaf(a, x4[j].z, yacc[j * 4 + 2]);
                yacc[j * 4 + 3] = fmaf(a, x4[j].w, yacc[j * 4 + 3]);
            }
        }

        for (int i = threadIdx.x; i < VV; i += 128) sh[i] = 0.f;
        if (threadIdx.x == 0) shA = 0.f;
        __syncthreads();
#pragma unroll
        for (int j = 0; j < 8; j++) {
            int col = j * 128 + lane * 4;
            atomicAdd(&sh[col + 0], yacc[j * 4 + 0]);
            atomicAdd(&sh[col + 1], yacc[j * 4 + 1]);
            atomicAdd(&sh[col + 2], yacc[j * 4 + 2]);
            atomicAdd(&sh[col + 3], yacc[j * 4 + 3]);
        }
        if (lane == 0) atomicAdd(&shA, Aacc);
        __syncthreads();
        for (int i = threadIdx.x; i < VV; i += 128)
            atomicAdd(&g_y[(size_t)b * VV + i], sh[i]);
        if (threadIdx.x == 0) atomicAdd(&g_A[b], shA);
    }
    gbar();

    // ---------- Phase D: out[b][o] = Wv[o].y[b] + A[b]*bv[o] ----------
    if (blockIdx.x < 256) {
        const int o = blockIdx.x * 4 + warp;
        float acc[16];
#pragma unroll
        for (int b = 0; b < 16; b++) acc[b] = 0.f;

        for (int ch = 0; ch < 4; ch++) {
            __syncthreads();
            for (int i = threadIdx.x; i < 4096; i += 128) {
                int b = i >> 8, v = i & 255;
                sh[i] = g_y[(size_t)b * VV + ch * 256 + v];
            }
            __syncthreads();
#pragma unroll
            for (int j = 0; j < 8; j++) {
                float w = Wv[(size_t)o * VV + ch * 256 + j * 32 + lane];
#pragma unroll
                for (int b = 0; b < 16; b++)
                    acc[b] = fmaf(w, sh[b * 256 + j * 32 + lane], acc[b]);
            }
        }
#pragma unroll
        for (int b = 0; b < 16; b++) {
#pragma unroll
            for (int off = 16; off; off >>= 1)
                acc[b] += __shfl_xor_sync(0xffffffffu, acc[b], off);
        }
        if (lane == 0) {
            float bvo = bv[o];
#pragma unroll
            for (int b = 0; b < 16; b++)
                out[(size_t)b * VV + o] = acc[b] + g_A[b] * bvo;
        }
    }
}

// ---------------------------------------------------------------------------
extern "C" void kernel_launch(void* const* d_in, const int* in_sizes, int n_in,
                              void* d_out, int out_size) {
    const float* pool = (const float*)d_in[0];
    const float* bert = (const float*)d_in[1];
    const float* Wq   = (const float*)d_in[2];
    const float* bq   = (const float*)d_in[3];
    const float* Wk   = (const float*)d_in[4];
    const float* bk   = (const float*)d_in[5];
    const float* Wv   = (const float*)d_in[6];
    const float* bv   = (const float*)d_in[7];
    float* out = (float*)d_out;

    fused_kernel<<<NB, 128>>>(pool, bert, Wq, bq, Wk, bk, Wv, bv, out);
}